// round 1
// baseline (speedup 1.0000x reference)
#include <cuda_runtime.h>
#include <math.h>
#include <stdint.h>

// Problem constants
#define NN 32768        // B*K rows
#define DD 256          // feature dim
#define EE 8192         // codebook entries
#define ND (NN*DD)      // 8388608

// ---------------- scratch (static __device__, no allocation) ----------------
__device__ __align__(16) float g_flatn[NN * DD];   // normalized inputs
__device__ __align__(16) float g_coden[EE * DD];   // normalized codebook
__device__ float g_partial[NN / 8];                // per-block norm sums
__device__ float g_scale;                          // mean input norm
__device__ int   g_idx[NN];
__device__ float g_sim[NN];
__device__ int   g_counts[EE];

// ---------------- zero counts ----------------
__global__ void zero_counts_kernel() {
    g_counts[blockIdx.x * 256 + threadIdx.x] = 0;
}

// ---------------- row L2-normalize, inputs (+ per-block norm sum) -----------
__global__ void normalize_inputs_kernel(const float* __restrict__ in) {
    int warp = threadIdx.x >> 5, lane = threadIdx.x & 31;
    int row = blockIdx.x * 8 + warp;
    __shared__ float sh[8];
    float nrm = 0.f;
    const float4* r = (const float4*)in + (size_t)row * 64;
    float4 v0 = r[lane], v1 = r[lane + 32];
    float s = v0.x*v0.x + v0.y*v0.y + v0.z*v0.z + v0.w*v0.w
            + v1.x*v1.x + v1.y*v1.y + v1.z*v1.z + v1.w*v1.w;
#pragma unroll
    for (int off = 16; off; off >>= 1) s += __shfl_down_sync(0xffffffffu, s, off);
    s = __shfl_sync(0xffffffffu, s, 0);
    nrm = sqrtf(s);
    float inv = 1.0f / fmaxf(nrm, 1e-12f);
    float4* o = (float4*)g_flatn + (size_t)row * 64;
    v0.x *= inv; v0.y *= inv; v0.z *= inv; v0.w *= inv;
    v1.x *= inv; v1.y *= inv; v1.z *= inv; v1.w *= inv;
    o[lane] = v0; o[lane + 32] = v1;

    if (lane == 0) sh[warp] = nrm;
    __syncthreads();
    if (threadIdx.x == 0) {
        float t = 0.f;
#pragma unroll
        for (int w = 0; w < 8; w++) t += sh[w];
        g_partial[blockIdx.x] = t;
    }
}

// ---------------- row L2-normalize, codebook --------------------------------
__global__ void normalize_codebook_kernel(const float* __restrict__ in) {
    int warp = threadIdx.x >> 5, lane = threadIdx.x & 31;
    int row = blockIdx.x * 8 + warp;
    const float4* r = (const float4*)in + (size_t)row * 64;
    float4 v0 = r[lane], v1 = r[lane + 32];
    float s = v0.x*v0.x + v0.y*v0.y + v0.z*v0.z + v0.w*v0.w
            + v1.x*v1.x + v1.y*v1.y + v1.z*v1.z + v1.w*v1.w;
#pragma unroll
    for (int off = 16; off; off >>= 1) s += __shfl_down_sync(0xffffffffu, s, off);
    s = __shfl_sync(0xffffffffu, s, 0);
    float inv = 1.0f / fmaxf(sqrtf(s), 1e-12f);
    float4* o = (float4*)g_coden + (size_t)row * 64;
    v0.x *= inv; v0.y *= inv; v0.z *= inv; v0.w *= inv;
    v1.x *= inv; v1.y *= inv; v1.z *= inv; v1.w *= inv;
    o[lane] = v0; o[lane + 32] = v1;
}

// ---------------- deterministic mean-scale reduction ------------------------
__global__ void reduce_scale_kernel() {
    __shared__ float sh[256];
    float s = 0.f;
    for (int i = threadIdx.x; i < NN / 8; i += 256) s += g_partial[i];
    sh[threadIdx.x] = s; __syncthreads();
    for (int off = 128; off; off >>= 1) {
        if (threadIdx.x < off) sh[threadIdx.x] += sh[threadIdx.x + off];
        __syncthreads();
    }
    if (threadIdx.x == 0) g_scale = sh[0] / (float)NN;
}

// ---------------- fused argmax GEMM -----------------------------------------
// 128x128 tile per block, 8x8 per thread, BK=32 k-tiles, k-major shared tiles.
__global__ __launch_bounds__(256) void argmax_gemm_kernel() {
    __shared__ float As[32][132];
    __shared__ float Bs[32][132];
    const int tid = threadIdx.x;
    const int tx = tid & 15;       // 0..15 -> code columns
    const int ty = tid >> 4;       // 0..15 -> rows
    const int row0 = blockIdx.x * 128;

    const float4* A4 = (const float4*)g_flatn;
    const float4* B4 = (const float4*)g_coden;

    float best[8];
    int   bidx[8];
#pragma unroll
    for (int i = 0; i < 8; i++) { best[i] = -1e30f; bidx[i] = 0; }

    for (int e0 = 0; e0 < EE; e0 += 128) {
        float acc[8][8];
#pragma unroll
        for (int i = 0; i < 8; i++)
#pragma unroll
            for (int j = 0; j < 8; j++) acc[i][j] = 0.f;

        for (int k0 = 0; k0 < DD; k0 += 32) {
            // load + transpose 128x32 tiles of A and B into shared (k-major)
#pragma unroll
            for (int l = 0; l < 4; ++l) {
                int s  = tid + l * 256;       // 0..1023 float4 slots
                int r  = s >> 3;              // row within tile (0..127)
                int kq = s & 7;               // float4 within k-tile (0..7)
                float4 va = A4[(size_t)(row0 + r) * 64 + (k0 >> 2) + kq];
                As[kq*4+0][r] = va.x; As[kq*4+1][r] = va.y;
                As[kq*4+2][r] = va.z; As[kq*4+3][r] = va.w;
                float4 vb = B4[(size_t)(e0 + r) * 64 + (k0 >> 2) + kq];
                Bs[kq*4+0][r] = vb.x; Bs[kq*4+1][r] = vb.y;
                Bs[kq*4+2][r] = vb.z; Bs[kq*4+3][r] = vb.w;
            }
            __syncthreads();
#pragma unroll
            for (int kk = 0; kk < 32; ++kk) {
                float4 a0 = *(const float4*)&As[kk][ty * 8];
                float4 a1 = *(const float4*)&As[kk][ty * 8 + 4];
                float4 b0 = *(const float4*)&Bs[kk][tx * 4];
                float4 b1 = *(const float4*)&Bs[kk][tx * 4 + 64];
                float a[8] = {a0.x,a0.y,a0.z,a0.w,a1.x,a1.y,a1.z,a1.w};
                float b[8] = {b0.x,b0.y,b0.z,b0.w,b1.x,b1.y,b1.z,b1.w};
#pragma unroll
                for (int i = 0; i < 8; i++)
#pragma unroll
                    for (int j = 0; j < 8; j++)
                        acc[i][j] += a[i] * b[j];
            }
            __syncthreads();
        }
        // argmax update (ties -> lowest index, matches jnp.argmin(-sim))
#pragma unroll
        for (int i = 0; i < 8; i++) {
#pragma unroll
            for (int j = 0; j < 8; j++) {
                int e = e0 + ((j < 4) ? (tx * 4 + j) : (64 + tx * 4 + (j - 4)));
                float v = acc[i][j];
                if (v > best[i] || (v == best[i] && e < bidx[i])) {
                    best[i] = v; bidx[i] = e;
                }
            }
        }
    }

    // reduce across the 16 tx-threads (contiguous 16-lane segments)
#pragma unroll
    for (int i = 0; i < 8; i++) {
        float v = best[i]; int bi = bidx[i];
#pragma unroll
        for (int off = 8; off > 0; off >>= 1) {
            float ov = __shfl_down_sync(0xffffffffu, v,  off, 16);
            int   oi = __shfl_down_sync(0xffffffffu, bi, off, 16);
            if (ov > v || (ov == v && oi < bi)) { v = ov; bi = oi; }
        }
        if (tx == 0) {
            int row = row0 + ty * 8 + i;
            g_idx[row] = bi;
            g_sim[row] = v;
        }
    }
}

// ---------------- bincount (integer atomics: deterministic) -----------------
__global__ void bincount_kernel() {
    int i = blockIdx.x * 256 + threadIdx.x;
    atomicAdd(&g_counts[g_idx[i]], 1);
}

// ---------------- quantized output ------------------------------------------
__global__ void write_quant_kernel(float* __restrict__ out) {
    int i = blockIdx.x * 256 + threadIdx.x;   // float4 index over N*64
    float s = g_scale;
    int n = i >> 6, d4 = i & 63;
    float4 v = ((const float4*)g_coden)[(size_t)g_idx[n] * 64 + d4];
    v.x *= s; v.y *= s; v.z *= s; v.w *= s;
    ((float4*)out)[i] = v;
}

// ---------------- loss + perplexity -----------------------------------------
__global__ void finalize_kernel(float* __restrict__ out) {
    __shared__ float sh[256];
    int tid = threadIdx.x;

    // sum of best similarities (fixed strided order -> deterministic)
    float s = 0.f;
    for (int i = tid; i < NN; i += 256) s += g_sim[i];
    sh[tid] = s; __syncthreads();
    for (int off = 128; off; off >>= 1) {
        if (tid < off) sh[tid] += sh[tid + off];
        __syncthreads();
    }
    float sumS = sh[0];
    __syncthreads();

    // entropy of code usage
    float h = 0.f;
    for (int i = tid; i < EE; i += 256) {
        float p = (float)g_counts[i] / (float)NN;
        h -= p * logf(p + 1e-10f);
    }
    sh[tid] = h; __syncthreads();
    for (int off = 128; off; off >>= 1) {
        if (tid < off) sh[tid] += sh[tid + off];
        __syncthreads();
    }
    if (tid == 0) {
        // ||qn - fn||^2 = 2 - 2*sim  (both unit vectors)
        float loss = 1.25f * (2.0f * (float)NN - 2.0f * sumS) / (float)ND;
        out[ND]     = loss;
        out[ND + 1] = expf(sh[0]);
    }
}

// ---------------- launch ----------------------------------------------------
extern "C" void kernel_launch(void* const* d_in, const int* in_sizes, int n_in,
                              void* d_out, int out_size) {
    const float* inputs   = (const float*)d_in[0];   // [32,1024,256] f32
    const float* codebook = (const float*)d_in[1];   // [8192,256] f32
    float* out = (float*)d_out;

    zero_counts_kernel<<<EE / 256, 256>>>();
    normalize_inputs_kernel<<<NN / 8, 256>>>(inputs);
    normalize_codebook_kernel<<<EE / 8, 256>>>(codebook);
    reduce_scale_kernel<<<1, 256>>>();
    argmax_gemm_kernel<<<NN / 128, 256>>>();
    bincount_kernel<<<NN / 256, 256>>>();
    write_quant_kernel<<<ND / 4 / 256, 256>>>(out);
    finalize_kernel<<<1, 256>>>(out);
}

// round 3
// speedup vs baseline: 6.1209x; 6.1209x over previous
#include <cuda_runtime.h>
#include <cuda_bf16.h>
#include <math.h>
#include <stdint.h>

// Problem constants
#define NN 32768        // B*K rows
#define DD 256          // feature dim
#define EE 8192         // codebook entries
#define ND (NN*DD)
#define CAP 64          // candidate list capacity per row
#define MARGIN 0.012f   // bf16 rounding slack (2 * 2 * 2^-9 + headroom)

// ---------------- scratch (static __device__, no allocation) ----------------
__device__ __align__(16) __nv_bfloat16 g_Abf[NN * DD];
__device__ __align__(16) __nv_bfloat16 g_Bbf[EE * DD];
__device__ __align__(16) float g_flatn[NN * DD];   // fp32 normalized inputs
__device__ __align__(16) float g_coden[EE * DD];   // fp32 normalized codebook
__device__ float g_partial[NN / 8];
__device__ float g_scale;
__device__ int   g_idx[NN];
__device__ float g_sim[NN];
__device__ int   g_counts[EE];
__device__ int   g_ccnt[NN];
__device__ int   g_cand[NN * CAP];

// ---------------- PTX helpers ----------------
__device__ __forceinline__ uint32_t smem_u32(const void* p) {
    uint32_t a;
    asm("{ .reg .u64 t; cvta.to.shared.u64 t, %1; cvt.u32.u64 %0, t; }" : "=r"(a) : "l"(p));
    return a;
}
#define CP_ASYNC16(dst, src) \
    asm volatile("cp.async.cg.shared.global [%0], [%1], 16;" :: "r"(dst), "l"(src) : "memory")
#define CP_COMMIT() asm volatile("cp.async.commit_group;" ::: "memory")
#define CP_WAIT1()  asm volatile("cp.async.wait_group 1;" ::: "memory")
#define CP_WAIT0()  asm volatile("cp.async.wait_group 0;" ::: "memory")
#define LDMATRIX_X4(r0, r1, r2, r3, addr) \
    asm volatile("ldmatrix.sync.aligned.m8n8.x4.shared.b16 {%0,%1,%2,%3}, [%4];" \
        : "=r"(r0), "=r"(r1), "=r"(r2), "=r"(r3) : "r"(addr))
#define MMA16816(c, a, b0, b1) \
    asm volatile("mma.sync.aligned.m16n8k16.row.col.f32.bf16.bf16.f32 " \
        "{%0,%1,%2,%3}, {%4,%5,%6,%7}, {%8,%9}, {%0,%1,%2,%3};" \
        : "+f"((c)[0]), "+f"((c)[1]), "+f"((c)[2]), "+f"((c)[3]) \
        : "r"((a)[0]), "r"((a)[1]), "r"((a)[2]), "r"((a)[3]), "r"(b0), "r"(b1))

// ---------------- zero counters ----------------
__global__ void zero_kernel() {
    int i = blockIdx.x * 256 + threadIdx.x;
    if (i < EE) g_counts[i] = 0;
    if (i < NN) g_ccnt[i] = 0;
}

// ---------------- normalize inputs -> fp32 + bf16 + norm sums ----------------
__global__ void normalize_inputs_kernel(const float* __restrict__ in) {
    int warp = threadIdx.x >> 5, lane = threadIdx.x & 31;
    int row = blockIdx.x * 8 + warp;
    __shared__ float sh[8];
    const float4* r = (const float4*)in + (size_t)row * 64;
    float4 v0 = r[lane], v1 = r[lane + 32];
    float s = v0.x*v0.x + v0.y*v0.y + v0.z*v0.z + v0.w*v0.w
            + v1.x*v1.x + v1.y*v1.y + v1.z*v1.z + v1.w*v1.w;
#pragma unroll
    for (int off = 16; off; off >>= 1) s += __shfl_down_sync(0xffffffffu, s, off);
    s = __shfl_sync(0xffffffffu, s, 0);
    float nrm = sqrtf(s);
    float inv = 1.0f / fmaxf(nrm, 1e-12f);
    float4 n0 = make_float4(v0.x*inv, v0.y*inv, v0.z*inv, v0.w*inv);
    float4 n1 = make_float4(v1.x*inv, v1.y*inv, v1.z*inv, v1.w*inv);
    ((float4*)g_flatn)[(size_t)row * 64 + lane]      = n0;
    ((float4*)g_flatn)[(size_t)row * 64 + 32 + lane] = n1;
    __nv_bfloat162 b0 = __floats2bfloat162_rn(n0.x, n0.y);
    __nv_bfloat162 b1 = __floats2bfloat162_rn(n0.z, n0.w);
    __nv_bfloat162 b2 = __floats2bfloat162_rn(n1.x, n1.y);
    __nv_bfloat162 b3 = __floats2bfloat162_rn(n1.z, n1.w);
    uint2 h0 = make_uint2(*(uint32_t*)&b0, *(uint32_t*)&b1);
    uint2 h1 = make_uint2(*(uint32_t*)&b2, *(uint32_t*)&b3);
    ((uint2*)g_Abf)[(size_t)row * 64 + lane]      = h0;
    ((uint2*)g_Abf)[(size_t)row * 64 + 32 + lane] = h1;

    if (lane == 0) sh[warp] = nrm;
    __syncthreads();
    if (threadIdx.x == 0) {
        float t = 0.f;
#pragma unroll
        for (int w = 0; w < 8; w++) t += sh[w];
        g_partial[blockIdx.x] = t;
    }
}

// ---------------- normalize codebook -> fp32 + bf16 -------------------------
__global__ void normalize_codebook_kernel(const float* __restrict__ in) {
    int warp = threadIdx.x >> 5, lane = threadIdx.x & 31;
    int row = blockIdx.x * 8 + warp;
    const float4* r = (const float4*)in + (size_t)row * 64;
    float4 v0 = r[lane], v1 = r[lane + 32];
    float s = v0.x*v0.x + v0.y*v0.y + v0.z*v0.z + v0.w*v0.w
            + v1.x*v1.x + v1.y*v1.y + v1.z*v1.z + v1.w*v1.w;
#pragma unroll
    for (int off = 16; off; off >>= 1) s += __shfl_down_sync(0xffffffffu, s, off);
    s = __shfl_sync(0xffffffffu, s, 0);
    float inv = 1.0f / fmaxf(sqrtf(s), 1e-12f);
    float4 n0 = make_float4(v0.x*inv, v0.y*inv, v0.z*inv, v0.w*inv);
    float4 n1 = make_float4(v1.x*inv, v1.y*inv, v1.z*inv, v1.w*inv);
    ((float4*)g_coden)[(size_t)row * 64 + lane]      = n0;
    ((float4*)g_coden)[(size_t)row * 64 + 32 + lane] = n1;
    __nv_bfloat162 b0 = __floats2bfloat162_rn(n0.x, n0.y);
    __nv_bfloat162 b1 = __floats2bfloat162_rn(n0.z, n0.w);
    __nv_bfloat162 b2 = __floats2bfloat162_rn(n1.x, n1.y);
    __nv_bfloat162 b3 = __floats2bfloat162_rn(n1.z, n1.w);
    uint2 h0 = make_uint2(*(uint32_t*)&b0, *(uint32_t*)&b1);
    uint2 h1 = make_uint2(*(uint32_t*)&b2, *(uint32_t*)&b3);
    ((uint2*)g_Bbf)[(size_t)row * 64 + lane]      = h0;
    ((uint2*)g_Bbf)[(size_t)row * 64 + 32 + lane] = h1;
}

// ---------------- deterministic mean-scale reduction ------------------------
__global__ void reduce_scale_kernel() {
    __shared__ float sh[256];
    float s = 0.f;
    for (int i = threadIdx.x; i < NN / 8; i += 256) s += g_partial[i];
    sh[threadIdx.x] = s; __syncthreads();
    for (int off = 128; off; off >>= 1) {
        if (threadIdx.x < off) sh[threadIdx.x] += sh[threadIdx.x + off];
        __syncthreads();
    }
    if (threadIdx.x == 0) g_scale = sh[0] / (float)NN;
}

// ---------------- bf16 mma.sync GEMM + running max + candidate capture ------
// 128x128 CTA tile, 8 warps in 4m x 2n grid (warp tile 32x64), A resident in
// smem (128x256 bf16, XOR-swizzled), B streamed in 128x64 k-chunks,
// double-buffered cp.async.
// smem layout: A at 0 (65536 B), B stages at 65536 + buf*16384.
#define SMEM_GEMM (65536 + 2 * 16384)

__device__ __forceinline__ uint32_t a_off(uint32_t r, uint32_t ch) {
    return r * 512u + (((ch & 0x18u) | ((ch ^ r) & 7u)) << 4);
}
__device__ __forceinline__ uint32_t b_off(uint32_t c, uint32_t ch) {
    return c * 128u + (((ch ^ c) & 7u) << 4);
}

__global__ void __launch_bounds__(256, 2) hh_gemm_kernel() {
    extern __shared__ __align__(1024) char smem[];
    const uint32_t sb = smem_u32(smem);
    const int tid = threadIdx.x;
    const int wid = tid >> 5;
    const int lane = tid & 31;
    const int warp_m = wid & 3;
    const int warp_n = wid >> 2;
    const int row0 = blockIdx.x * 128;

    // ---- A resident load (group 0) ----
    {
        const uint4* Ag = (const uint4*)g_Abf;
#pragma unroll
        for (int l = 0; l < 16; l++) {
            int id = tid + l * 256;          // 0..4095
            uint32_t r = id >> 5, ch = id & 31;
            uint32_t dst = sb + a_off(r, ch);
            const uint4* src = Ag + (size_t)(row0 + r) * 32 + ch;
            CP_ASYNC16(dst, src);
        }
    }
    CP_COMMIT();

    const uint4* Bg = (const uint4*)g_Bbf;
    // issue stage i: tile t = i>>2, k-chunk kc = i&3, buffer i&1
#define ISSUE_STAGE(i) do { \
        int _t = (i) >> 2, _kc = (i) & 3; \
        uint32_t _bb = sb + 65536 + ((i) & 1) * 16384; \
        _Pragma("unroll") \
        for (int _l = 0; _l < 4; _l++) { \
            int _id = tid + _l * 256; \
            uint32_t _c = _id >> 3, _ch = _id & 7; \
            uint32_t _dst = _bb + b_off(_c, _ch); \
            const uint4* _src = Bg + (size_t)(_t * 128 + _c) * 32 + _kc * 8 + _ch; \
            CP_ASYNC16(_dst, _src); \
        } \
    } while (0)

    ISSUE_STAGE(0);
    CP_COMMIT();

    float c[2][8][4];
    float bestv[4] = {-1e30f, -1e30f, -1e30f, -1e30f};

    for (int i = 0; i < 256; i++) {
        const int kc = i & 3;
        const int t = i >> 2;
        if (i + 1 < 256) {
            ISSUE_STAGE(i + 1);
            CP_COMMIT();
            CP_WAIT1();
        } else {
            CP_WAIT0();
        }
        __syncthreads();

        if (kc == 0) {
#pragma unroll
            for (int mi = 0; mi < 2; mi++)
#pragma unroll
                for (int ni = 0; ni < 8; ni++)
#pragma unroll
                    for (int r2 = 0; r2 < 4; r2++) c[mi][ni][r2] = 0.f;
        }

        const uint32_t bb = sb + 65536 + (i & 1) * 16384;
#pragma unroll
        for (int ks = 0; ks < 4; ks++) {
            uint32_t a[2][4];
#pragma unroll
            for (int mi = 0; mi < 2; mi++) {
                uint32_t r = warp_m * 32 + mi * 16 + (lane & 15);
                uint32_t ch = kc * 8 + ks * 2 + (lane >> 4);
                uint32_t addr = sb + a_off(r, ch);
                LDMATRIX_X4(a[mi][0], a[mi][1], a[mi][2], a[mi][3], addr);
            }
            uint32_t b[4][4];
#pragma unroll
            for (int np = 0; np < 4; np++) {
                uint32_t code = warp_n * 64 + np * 16 + (lane & 7) + ((lane & 16) ? 8 : 0);
                uint32_t ch = ks * 2 + ((lane >> 3) & 1);
                uint32_t addr = bb + b_off(code, ch);
                LDMATRIX_X4(b[np][0], b[np][1], b[np][2], b[np][3], addr);
            }
#pragma unroll
            for (int mi = 0; mi < 2; mi++)
#pragma unroll
                for (int ni = 0; ni < 8; ni++)
                    MMA16816(c[mi][ni], a[mi], b[ni >> 1][(ni & 1) * 2], b[ni >> 1][(ni & 1) * 2 + 1]);
        }

        // ---- per-tile epilogue after last k-chunk ----
        if (kc == 3) {
#pragma unroll
            for (int s = 0; s < 4; s++) {
                const int mi = s >> 1, hf = s & 1;
                float m = c[mi][0][hf * 2];
#pragma unroll
                for (int ni = 0; ni < 8; ni++) {
                    m = fmaxf(m, c[mi][ni][hf * 2]);
                    m = fmaxf(m, c[mi][ni][hf * 2 + 1]);
                }
                m = fmaxf(m, __shfl_xor_sync(0xffffffffu, m, 1));
                m = fmaxf(m, __shfl_xor_sync(0xffffffffu, m, 2));
                bestv[s] = fmaxf(bestv[s], m);
                const float thr = bestv[s] - MARGIN;
                const int row = row0 + warp_m * 32 + mi * 16 + (lane >> 2) + hf * 8;
#pragma unroll
                for (int ni = 0; ni < 8; ni++) {
#pragma unroll
                    for (int r2 = 0; r2 < 2; r2++) {
                        float v = c[mi][ni][hf * 2 + r2];
                        if (v >= thr) {
                            int col = t * 128 + warp_n * 64 + ni * 8 + (lane & 3) * 2 + r2;
                            int slot = atomicAdd(&g_ccnt[row], 1);
                            if (slot < CAP) g_cand[row * CAP + slot] = col;
                        }
                    }
                }
            }
        }
        __syncthreads();
    }
}

// ---------------- exact fp32 refine over candidates -------------------------
__global__ void refine_kernel() {
    const int wid = threadIdx.x >> 5, lane = threadIdx.x & 31;
    const int row = blockIdx.x * 8 + wid;
    const float4* F = (const float4*)g_flatn + (size_t)row * 64 + lane * 2;
    const float4 f0 = F[0], f1 = F[1];
    int cnt = g_ccnt[row];
    float bv = -1e30f;
    int bi = 0x7fffffff;

    if (cnt <= CAP) {
        for (int j = 0; j < cnt; j++) {
            int cidx = g_cand[row * CAP + j];
            const float4* G = (const float4*)g_coden + (size_t)cidx * 64 + lane * 2;
            float4 g0 = G[0], g1 = G[1];
            float s = f0.x*g0.x + f0.y*g0.y + f0.z*g0.z + f0.w*g0.w
                    + f1.x*g1.x + f1.y*g1.y + f1.z*g1.z + f1.w*g1.w;
#pragma unroll
            for (int off = 16; off; off >>= 1) s += __shfl_xor_sync(0xffffffffu, s, off);
            if (s > bv || (s == bv && cidx < bi)) { bv = s; bi = cidx; }
        }
    } else {
        // overflow fallback: exact scan over all codes
        for (int cidx = 0; cidx < EE; cidx++) {
            const float4* G = (const float4*)g_coden + (size_t)cidx * 64 + lane * 2;
            float4 g0 = G[0], g1 = G[1];
            float s = f0.x*g0.x + f0.y*g0.y + f0.z*g0.z + f0.w*g0.w
                    + f1.x*g1.x + f1.y*g1.y + f1.z*g1.z + f1.w*g1.w;
#pragma unroll
            for (int off = 16; off; off >>= 1) s += __shfl_xor_sync(0xffffffffu, s, off);
            if (s > bv || (s == bv && cidx < bi)) { bv = s; bi = cidx; }
        }
    }
    if (lane == 0) {
        g_idx[row] = bi;
        g_sim[row] = bv;
    }
}

// ---------------- bincount ----------------
__global__ void bincount_kernel() {
    int i = blockIdx.x * 256 + threadIdx.x;
    atomicAdd(&g_counts[g_idx[i]], 1);
}

// ---------------- quantized output ----------------
__global__ void write_quant_kernel(float* __restrict__ out) {
    int i = blockIdx.x * 256 + threadIdx.x;
    float s = g_scale;
    int n = i >> 6, d4 = i & 63;
    float4 v = ((const float4*)g_coden)[(size_t)g_idx[n] * 64 + d4];
    v.x *= s; v.y *= s; v.z *= s; v.w *= s;
    ((float4*)out)[i] = v;
}

// ---------------- loss + perplexity ----------------
__global__ void finalize_kernel(float* __restrict__ out) {
    __shared__ float sh[256];
    int tid = threadIdx.x;
    float s = 0.f;
    for (int i = tid; i < NN; i += 256) s += g_sim[i];
    sh[tid] = s; __syncthreads();
    for (int off = 128; off; off >>= 1) {
        if (tid < off) sh[tid] += sh[tid + off];
        __syncthreads();
    }
    float sumS = sh[0];
    __syncthreads();
    float h = 0.f;
    for (int i = tid; i < EE; i += 256) {
        float p = (float)g_counts[i] / (float)NN;
        h -= p * logf(p + 1e-10f);
    }
    sh[tid] = h; __syncthreads();
    for (int off = 128; off; off >>= 1) {
        if (tid < off) sh[tid] += sh[tid + off];
        __syncthreads();
    }
    if (tid == 0) {
        float loss = 1.25f * (2.0f * (float)NN - 2.0f * sumS) / (float)ND;
        out[ND]     = loss;
        out[ND + 1] = expf(sh[0]);
    }
}

// ---------------- launch ----------------
extern "C" void kernel_launch(void* const* d_in, const int* in_sizes, int n_in,
                              void* d_out, int out_size) {
    const float* inputs   = (const float*)d_in[0];
    const float* codebook = (const float*)d_in[1];
    float* out = (float*)d_out;

    cudaFuncSetAttribute(hh_gemm_kernel, cudaFuncAttributeMaxDynamicSharedMemorySize, SMEM_GEMM);

    zero_kernel<<<NN / 256, 256>>>();
    normalize_inputs_kernel<<<NN / 8, 256>>>(inputs);
    normalize_codebook_kernel<<<EE / 8, 256>>>(codebook);
    reduce_scale_kernel<<<1, 256>>>();
    hh_gemm_kernel<<<NN / 128, 256, SMEM_GEMM>>>();
    refine_kernel<<<NN / 8, 256>>>();
    bincount_kernel<<<NN / 256, 256>>>();
    write_quant_kernel<<<ND / 4 / 256, 256>>>(out);
    finalize_kernel<<<1, 256>>>(out);
}